// round 8
// baseline (speedup 1.0000x reference)
#include <cuda_runtime.h>
#include <cstddef>

// Involution (B=8, H=W=192, C=64, G=4, K=3, R=4 -> cr=16)
// R8: 1 px/thread, 256 threads/block, 16x16 tile, channel-split smem tile,
// w1 in smem (LDS broadcast), w2/b2/b1 in __constant__ (LDC), <=64 regs ->
// 4 blocks x 8 warps = 32 warps/SM.

#define HH 192
#define WW 192
#define CC 64
#define CR 16
#define TAPS 9

constexpr int TILE = 16;
constexpr int HALO = 18;
constexpr int PSTR = 9;                               // f4 per pixel (8 data + 1 pad)
constexpr int TILE_F4 = HALO * HALO * PSTR;           // 2916
constexpr int W1_F4 = 256;                            // [c4=16][d=16], BN folded
constexpr int SMEM_BYTES = (TILE_F4 + W1_F4) * 16;    // 50752 B

struct ConstPart {
    float4 w2[144];   // [d=16][tap=9], f4 over 4 groups
    float4 b2[9];
    float  b1[16];    // BN-folded bias
};
struct Scratch {
    float4 w1[256];   // BN-folded first conv
    ConstPart c;
};
__constant__ ConstPart cW;
__device__ Scratch scratchW;

__global__ void involution_prep_kernel(const float* __restrict__ w1,
                                       const float* __restrict__ b1,
                                       const float* __restrict__ gamma,
                                       const float* __restrict__ beta,
                                       const float* __restrict__ mean,
                                       const float* __restrict__ var,
                                       const float* __restrict__ w2,
                                       const float* __restrict__ b2) {
    __shared__ float s[16];
    int tid = threadIdx.x;   // 256 threads
    if (tid < 16) {
        float sc = gamma[tid] * rsqrtf(var[tid] + 1e-3f);
        s[tid] = sc;
        scratchW.c.b1[tid] = (b1[tid] - mean[tid]) * sc + beta[tid];
    }
    __syncthreads();
    {
        int d  = tid & 15;
        int c4 = tid >> 4;
        float sc = s[d];
        scratchW.w1[tid] = make_float4(w1[(4 * c4 + 0) * CR + d] * sc,
                                       w1[(4 * c4 + 1) * CR + d] * sc,
                                       w1[(4 * c4 + 2) * CR + d] * sc,
                                       w1[(4 * c4 + 3) * CR + d] * sc);
    }
    if (tid < 144) scratchW.c.w2[tid] = ((const float4*)w2)[tid];
    if (tid < 9)   scratchW.c.b2[tid] = ((const float4*)b2)[tid];
}

__device__ __forceinline__ void fma4(float4& a, const float4& k, const float4& v) {
    a.x = fmaf(k.x, v.x, a.x);
    a.y = fmaf(k.y, v.y, a.y);
    a.z = fmaf(k.z, v.z, a.z);
    a.w = fmaf(k.w, v.w, a.w);
}

__global__ __launch_bounds__(256, 4)
void involution_fused_kernel(const float* __restrict__ x,
                             float* __restrict__ out) {
    extern __shared__ float4 sm4[];
    float4* tile4 = sm4;                      // [18*18 px][9 f4]
    float4* w1s   = sm4 + TILE_F4;            // [256]

    const int tid = threadIdx.x;              // 0..255
    const int tx  = tid & 15;
    const int ty  = tid >> 4;                 // 0..15
    const int gx0 = blockIdx.x * TILE;
    const int gy0 = blockIdx.y * TILE;
    const int bz  = blockIdx.z;

    const float* xb = x + (size_t)bz * ((size_t)HH * WW * CC);

    // ---- stage folded w1 into smem (coalesced, L2-cached) ----
    w1s[tid] = scratchW.w1[tid];

    // ---- load tile channel-half u0-7 (zero-padded SAME) ----
    #pragma unroll 2
    for (int s = tid; s < HALO * HALO * 8; s += 256) {
        int u   = s & 7;
        int pix = s >> 3;
        int py  = pix / HALO;
        int px  = pix - py * HALO;
        int gh  = gy0 - 1 + py;
        int gw  = gx0 - 1 + px;
        float4 v = make_float4(0.f, 0.f, 0.f, 0.f);
        if ((unsigned)gh < HH && (unsigned)gw < WW)
            v = ((const float4*)(xb + ((size_t)gh * WW + gw) * CC))[u];
        tile4[pix * PSTR + u] = v;
    }
    __syncthreads();

    // ---- phase B: t[d] = relu(x . w1' + b1') ----
    const int pc = (ty + 1) * HALO + (tx + 1);
    const float4* gp = (const float4*)(xb + ((size_t)(gy0 + ty) * WW + gx0 + tx) * CC);

    float t[CR];
    #pragma unroll
    for (int d = 0; d < CR; d++) t[d] = cW.b1[d];

    const float4* xc = tile4 + pc * PSTR;
    #pragma unroll
    for (int c4 = 0; c4 < 8; c4++) {               // first channel half from smem
        float4 xv = xc[c4];
        const float4* wr = w1s + c4 * 16;
        #pragma unroll
        for (int d = 0; d < CR; d++) {
            float4 w = wr[d];
            t[d] = fmaf(xv.x, w.x, fmaf(xv.y, w.y, fmaf(xv.z, w.z, fmaf(xv.w, w.w, t[d]))));
        }
    }
    #pragma unroll
    for (int c4 = 8; c4 < 16; c4++) {              // second channel half from global
        float4 xv = gp[c4];
        const float4* wr = w1s + c4 * 16;
        #pragma unroll
        for (int d = 0; d < CR; d++) {
            float4 w = wr[d];
            t[d] = fmaf(xv.x, w.x, fmaf(xv.y, w.y, fmaf(xv.z, w.z, fmaf(xv.w, w.w, t[d]))));
        }
    }
    #pragma unroll
    for (int d = 0; d < CR; d++) t[d] = fmaxf(t[d], 0.f);

    // ---- phase C: per-pixel 3x3 kernel (f4 over groups), weights from constant ----
    float4 k[TAPS];
    #pragma unroll
    for (int tap = 0; tap < TAPS; tap++) k[tap] = cW.b2[tap];
    #pragma unroll
    for (int d = 0; d < CR; d++) {
        float a = t[d];
        #pragma unroll
        for (int tap = 0; tap < TAPS; tap++) {
            float4 w = cW.w2[d * TAPS + tap];
            k[tap].x = fmaf(a, w.x, k[tap].x);
            k[tap].y = fmaf(a, w.y, k[tap].y);
            k[tap].z = fmaf(a, w.z, k[tap].z);
            k[tap].w = fmaf(a, w.w, k[tap].w);
        }
    }

    // ---- phase D: two channel-half passes ----
    float4* o = (float4*)(out + (((size_t)bz * HH + gy0 + ty) * WW + gx0 + tx) * CC);
    const int rowstep = HALO * PSTR;
    const float4* base = tile4 + (ty * HALO + tx) * PSTR;

    #pragma unroll
    for (int uh = 0; uh < 2; uh++) {
        if (uh) {
            __syncthreads();
            #pragma unroll 2
            for (int s = tid; s < HALO * HALO * 8; s += 256) {
                int u   = s & 7;
                int pix = s >> 3;
                int py  = pix / HALO;
                int px  = pix - py * HALO;
                int gh  = gy0 - 1 + py;
                int gw  = gx0 - 1 + px;
                float4 v = make_float4(0.f, 0.f, 0.f, 0.f);
                if ((unsigned)gh < HH && (unsigned)gw < WW)
                    v = ((const float4*)(xb + ((size_t)gh * WW + gw) * CC))[8 + u];
                tile4[pix * PSTR + u] = v;
            }
            __syncthreads();
        }
        #pragma unroll 2
        for (int u = 0; u < 8; u++) {
            float4 acc = make_float4(0.f, 0.f, 0.f, 0.f);
            #pragma unroll
            for (int dj = 0; dj < 3; dj++) {
                const float4* col = base + dj * PSTR + u;
                float4 r0 = col[0];
                float4 r1 = col[rowstep];
                float4 r2 = col[2 * rowstep];
                fma4(acc, k[dj],     r0);
                fma4(acc, k[3 + dj], r1);
                fma4(acc, k[6 + dj], r2);
            }
            o[uh * 8 + u] = acc;
        }
    }
}

extern "C" void kernel_launch(void* const* d_in, const int* in_sizes, int n_in,
                              void* d_out, int out_size) {
    const float* x     = (const float*)d_in[0];
    const float* w1    = (const float*)d_in[1];
    const float* b1    = (const float*)d_in[2];
    const float* gamma = (const float*)d_in[3];
    const float* beta  = (const float*)d_in[4];
    const float* mean  = (const float*)d_in[5];
    const float* var   = (const float*)d_in[6];
    const float* w2    = (const float*)d_in[7];
    const float* b2    = (const float*)d_in[8];
    float* out = (float*)d_out;

    int B = in_sizes[0] / (HH * WW * CC);

    // 1) fold BN + stage weights into device scratch
    involution_prep_kernel<<<1, 256>>>(w1, b1, gamma, beta, mean, var, w2, b2);

    // 2) copy the constant part into __constant__ (D2D memcpy node, capturable)
    static char* scratch_addr = nullptr;
    if (!scratch_addr) cudaGetSymbolAddress((void**)&scratch_addr, scratchW);
    cudaMemcpyToSymbolAsync(cW, scratch_addr + offsetof(Scratch, c),
                            sizeof(ConstPart), 0, cudaMemcpyDeviceToDevice, 0);

    // 3) main fused kernel
    static bool attr_set = false;
    if (!attr_set) {
        cudaFuncSetAttribute(involution_fused_kernel,
                             cudaFuncAttributeMaxDynamicSharedMemorySize, SMEM_BYTES);
        attr_set = true;
    }
    dim3 grid(WW / TILE, HH / TILE, B);   // 12 x 12 x 8
    dim3 block(256);
    involution_fused_kernel<<<grid, block, SMEM_BYTES>>>(x, out);
}